// round 6
// baseline (speedup 1.0000x reference)
#include <cuda_runtime.h>
#include <cuda_bf16.h>
#include <cuda_fp16.h>
#include <cstdint>
#include <math.h>

#define BB 2
#define LL 2048
#define DD 1024
#define HH 16
#define DHH 64
#define MM (BB * LL)   // 4096
#define L2E 1.4426950408889634f

// ---------------------------------------------------------------------------
// Scratch (__device__ globals: allocation-free rule)
// ---------------------------------------------------------------------------
__device__ __nv_bfloat16 g_xhi[MM * DD];
__device__ __nv_bfloat16 g_xlo[MM * DD];
__device__ __nv_bfloat16 g_aohi[MM * DD];
__device__ __nv_bfloat16 g_aolo[MM * DD];
__device__ __nv_bfloat16 g_wthi[4][DD * DD];
__device__ __nv_bfloat16 g_wtlo[4][DD * DD];

// attention operands, pre-split by the projection epilogues
__device__ __nv_bfloat16 g_qhi[MM * DD];  // pre-scaled by 0.125
__device__ __nv_bfloat16 g_qlo[MM * DD];
__device__ __nv_bfloat16 g_khi[MM * DD];
__device__ __nv_bfloat16 g_klo[MM * DD];
__device__ __half        g_vhi[MM * DD];
__device__ __half        g_vlo[MM * DD];

// ---------------------------------------------------------------------------
// PTX helpers (portable sm_80+ subset; plain sm_103 target — no tcgen05)
// ---------------------------------------------------------------------------
__device__ __forceinline__ uint32_t smem_to_u32(const void* p) {
    uint32_t a;
    asm("{ .reg .u64 t; cvta.to.shared.u64 t, %1; cvt.u32.u64 %0, t; }"
        : "=r"(a) : "l"(p));
    return a;
}
__device__ __forceinline__ void cpasync16(uint32_t s, const void* g) {
    asm volatile("cp.async.cg.shared.global [%0], [%1], 16;" :: "r"(s), "l"(g));
}
__device__ __forceinline__ void cpcommit() {
    asm volatile("cp.async.commit_group;" ::: "memory");
}
template <int N>
__device__ __forceinline__ void cpwait() {
    asm volatile("cp.async.wait_group %0;" :: "n"(N) : "memory");
}
__device__ __forceinline__ void ldsm4(uint32_t* r, uint32_t addr) {
    asm volatile("ldmatrix.sync.aligned.m8n8.x4.shared.b16 {%0,%1,%2,%3}, [%4];"
                 : "=r"(r[0]), "=r"(r[1]), "=r"(r[2]), "=r"(r[3]) : "r"(addr));
}
__device__ __forceinline__ void ldsm4t(uint32_t* r, uint32_t addr) {
    asm volatile("ldmatrix.sync.aligned.m8n8.x4.trans.shared.b16 {%0,%1,%2,%3}, [%4];"
                 : "=r"(r[0]), "=r"(r[1]), "=r"(r[2]), "=r"(r[3]) : "r"(addr));
}
__device__ __forceinline__ void mma_bf16(float* d, const uint32_t* a, const uint32_t* b) {
    asm volatile(
        "mma.sync.aligned.m16n8k16.row.col.f32.bf16.bf16.f32 "
        "{%0,%1,%2,%3}, {%4,%5,%6,%7}, {%8,%9}, {%0,%1,%2,%3};"
        : "+f"(d[0]), "+f"(d[1]), "+f"(d[2]), "+f"(d[3])
        : "r"(a[0]), "r"(a[1]), "r"(a[2]), "r"(a[3]), "r"(b[0]), "r"(b[1]));
}
__device__ __forceinline__ void mma_f16(float* d, const uint32_t* a, const uint32_t* b) {
    asm volatile(
        "mma.sync.aligned.m16n8k16.row.col.f32.f16.f16.f32 "
        "{%0,%1,%2,%3}, {%4,%5,%6,%7}, {%8,%9}, {%0,%1,%2,%3};"
        : "+f"(d[0]), "+f"(d[1]), "+f"(d[2]), "+f"(d[3])
        : "r"(a[0]), "r"(a[1]), "r"(a[2]), "r"(a[3]), "r"(b[0]), "r"(b[1]));
}
__device__ __forceinline__ uint32_t cvt_f16x2(float hi, float lo) {
    uint32_t r;
    asm volatile("cvt.rn.f16x2.f32 %0, %1, %2;" : "=r"(r) : "f"(hi), "f"(lo));
    return r;
}
__device__ __forceinline__ uint32_t ex2_f16x2(uint32_t x) {
    uint32_t r;
    asm volatile("ex2.approx.f16x2 %0, %1;" : "=r"(r) : "r"(x));
    return r;
}

// ---------------------------------------------------------------------------
// Prep kernels
// ---------------------------------------------------------------------------
__global__ __launch_bounds__(256) void split_kernel(const float* __restrict__ in)
{
    int i = blockIdx.x * blockDim.x + threadIdx.x;
    float4 v = ((const float4*)in)[i];
    __nv_bfloat16 h0 = __float2bfloat16(v.x);
    __nv_bfloat16 h1 = __float2bfloat16(v.y);
    __nv_bfloat16 h2 = __float2bfloat16(v.z);
    __nv_bfloat16 h3 = __float2bfloat16(v.w);
    __nv_bfloat162* hp = (__nv_bfloat162*)g_xhi;
    __nv_bfloat162* lp = (__nv_bfloat162*)g_xlo;
    hp[2 * i]     = __nv_bfloat162(h0, h1);
    hp[2 * i + 1] = __nv_bfloat162(h2, h3);
    lp[2 * i]     = __nv_bfloat162(__float2bfloat16(v.x - __bfloat162float(h0)),
                                   __float2bfloat16(v.y - __bfloat162float(h1)));
    lp[2 * i + 1] = __nv_bfloat162(__float2bfloat16(v.z - __bfloat162float(h2)),
                                   __float2bfloat16(v.w - __bfloat162float(h3)));
}

__global__ __launch_bounds__(1024) void wsplit_kernel(const float* __restrict__ wq,
                                                      const float* __restrict__ wk,
                                                      const float* __restrict__ wv,
                                                      const float* __restrict__ wo)
{
    __shared__ float t[32][33];
    int which = blockIdx.z;
    const float* w = (which == 0) ? wq : (which == 1) ? wk : (which == 2) ? wv : wo;
    int kk = blockIdx.y * 32 + threadIdx.y;
    int nn = blockIdx.x * 32 + threadIdx.x;
    t[threadIdx.y][threadIdx.x] = w[kk * DD + nn];
    __syncthreads();
    int on = blockIdx.x * 32 + threadIdx.y;
    int ok = blockIdx.y * 32 + threadIdx.x;
    float v = t[threadIdx.x][threadIdx.y];
    __nv_bfloat16 h = __float2bfloat16(v);
    g_wthi[which][on * DD + ok] = h;
    g_wtlo[which][on * DD + ok] = __float2bfloat16(v - __bfloat162float(h));
}

// ---------------------------------------------------------------------------
// Split-bf16 HMMA GEMM, 512 threads, warp grid 4x4, 32x32 warp tile,
// BK=32, 3-stage cp.async pipeline. No register spills (~100 regs).
// mode 0: fp32 C; 1: bf16 split *0.125 (Q); 2: bf16 split (K); 3: f16 split (V)
// ---------------------------------------------------------------------------
#define BK 32
#define APITCH 40
#define BUF_BYTES (128 * APITCH * 2)        // 10240 per operand buffer
#define GEMM_STAGE (4 * BUF_BYTES)          // 40960
#define GEMM_SMEM_BYTES (3 * GEMM_STAGE)    // 122880

__device__ __forceinline__ void load_stage(uint32_t sbase, int stage,
                                           const __nv_bfloat16* __restrict__ Ahi,
                                           const __nv_bfloat16* __restrict__ Alo,
                                           const __nv_bfloat16* __restrict__ Bhi,
                                           const __nv_bfloat16* __restrict__ Blo,
                                           int m0, int n0, int k0, int tid)
{
    uint32_t so = sbase + stage * GEMM_STAGE;
    int row = tid >> 2;
    int col = (tid & 3) << 3;
    uint32_t soff = (uint32_t)(row * APITCH + col) * 2;
    size_t ga = (size_t)(m0 + row) * DD + k0 + col;
    size_t gb = (size_t)(n0 + row) * DD + k0 + col;
    cpasync16(so + 0 * BUF_BYTES + soff, Ahi + ga);
    cpasync16(so + 1 * BUF_BYTES + soff, Alo + ga);
    cpasync16(so + 2 * BUF_BYTES + soff, Bhi + gb);
    cpasync16(so + 3 * BUF_BYTES + soff, Blo + gb);
}

__device__ __forceinline__ void gemm_tc_body(const __nv_bfloat16* __restrict__ Ahi,
                                             const __nv_bfloat16* __restrict__ Alo,
                                             const __nv_bfloat16* __restrict__ Bhi,
                                             const __nv_bfloat16* __restrict__ Blo,
                                             const float* __restrict__ bias,
                                             float* __restrict__ C,
                                             int mode, void* oHi, void* oLo)
{
    extern __shared__ char smem[];
    const uint32_t sbase = smem_to_u32(smem);

    const int tid = threadIdx.x;
    const int lane = tid & 31;
    const int wid = tid >> 5;
    const int wm = (wid >> 2) * 32;     // 0,32,64,96
    const int wn = (wid & 3) * 32;      // 0,32,64,96
    const int m0 = blockIdx.y * 128;
    const int n0 = blockIdx.x * 128;

    const int a_row = wm + (lane & 15);
    const int a_col = (lane >> 4) << 3;
    const int b_row = wn + ((lane >> 4) << 3) + (lane & 7);
    const int b_col = ((lane >> 3) & 1) << 3;

    float acc[2][4][4];
#pragma unroll
    for (int i = 0; i < 2; i++)
#pragma unroll
        for (int j = 0; j < 4; j++)
#pragma unroll
            for (int r = 0; r < 4; r++) acc[i][j][r] = 0.f;

    load_stage(sbase, 0, Ahi, Alo, Bhi, Blo, m0, n0, 0, tid);
    cpcommit();
    load_stage(sbase, 1, Ahi, Alo, Bhi, Blo, m0, n0, BK, tid);
    cpcommit();

    const int NT = DD / BK;             // 32
    int st_idx = 0;
    for (int kt = 0; kt < NT; kt++) {
        if (kt + 2 < NT) {
            int ps = st_idx + 2; if (ps >= 3) ps -= 3;
            load_stage(sbase, ps, Ahi, Alo, Bhi, Blo, m0, n0, (kt + 2) * BK, tid);
            cpcommit();
            cpwait<2>();
        } else if (kt + 1 < NT) {
            cpwait<1>();
        } else {
            cpwait<0>();
        }
        __syncthreads();

        const uint32_t st = sbase + st_idx * GEMM_STAGE;
#pragma unroll
        for (int ks = 0; ks < 2; ks++) {
            const int kofs = ks * 16;
            uint32_t ah[2][4], al[2][4], bh[2][4], bl[2][4];
#pragma unroll
            for (int mt = 0; mt < 2; mt++) {
                uint32_t off = (uint32_t)((a_row + mt * 16) * APITCH + kofs + a_col) * 2;
                ldsm4(ah[mt], st + 0 * BUF_BYTES + off);
            }
#pragma unroll
            for (int nt2 = 0; nt2 < 2; nt2++) {
                uint32_t off = (uint32_t)((b_row + nt2 * 16) * APITCH + kofs + b_col) * 2;
                ldsm4(bh[nt2], st + 2 * BUF_BYTES + off);
            }
#pragma unroll
            for (int mt = 0; mt < 2; mt++)
#pragma unroll
                for (int nt = 0; nt < 4; nt++)
                    mma_bf16(acc[mt][nt], ah[mt], &bh[nt >> 1][(nt & 1) * 2]);
#pragma unroll
            for (int mt = 0; mt < 2; mt++) {
                uint32_t off = (uint32_t)((a_row + mt * 16) * APITCH + kofs + a_col) * 2;
                ldsm4(al[mt], st + 1 * BUF_BYTES + off);
            }
#pragma unroll
            for (int mt = 0; mt < 2; mt++)
#pragma unroll
                for (int nt = 0; nt < 4; nt++)
                    mma_bf16(acc[mt][nt], al[mt], &bh[nt >> 1][(nt & 1) * 2]);
#pragma unroll
            for (int nt2 = 0; nt2 < 2; nt2++) {
                uint32_t off = (uint32_t)((b_row + nt2 * 16) * APITCH + kofs + b_col) * 2;
                ldsm4(bl[nt2], st + 3 * BUF_BYTES + off);
            }
#pragma unroll
            for (int mt = 0; mt < 2; mt++)
#pragma unroll
                for (int nt = 0; nt < 4; nt++)
                    mma_bf16(acc[mt][nt], ah[mt], &bl[nt >> 1][(nt & 1) * 2]);
        }
        __syncthreads();
        if (++st_idx == 3) st_idx = 0;
    }

    const float sc = (mode == 1) ? 0.125f : 1.0f;
#pragma unroll
    for (int mt = 0; mt < 2; mt++) {
        int row = m0 + wm + mt * 16 + (lane >> 2);
#pragma unroll
        for (int nt = 0; nt < 4; nt++) {
            int col = n0 + wn + nt * 8 + 2 * (lane & 3);
            float b0 = bias[col], b1 = bias[col + 1];
            float v0 = acc[mt][nt][0] + b0, v1 = acc[mt][nt][1] + b1;
            float v2 = acc[mt][nt][2] + b0, v3 = acc[mt][nt][3] + b1;
            size_t off0 = (size_t)row * DD + col;
            size_t off1 = (size_t)(row + 8) * DD + col;
            if (mode == 0) {
                *(float2*)(C + off0) = make_float2(v0, v1);
                *(float2*)(C + off1) = make_float2(v2, v3);
            } else if (mode <= 2) {
                v0 *= sc; v1 *= sc; v2 *= sc; v3 *= sc;
                __nv_bfloat16 h0 = __float2bfloat16(v0), h1 = __float2bfloat16(v1);
                __nv_bfloat16 h2 = __float2bfloat16(v2), h3 = __float2bfloat16(v3);
                __nv_bfloat16* Hi = (__nv_bfloat16*)oHi;
                __nv_bfloat16* Lo = (__nv_bfloat16*)oLo;
                *(__nv_bfloat162*)(Hi + off0) = __nv_bfloat162(h0, h1);
                *(__nv_bfloat162*)(Hi + off1) = __nv_bfloat162(h2, h3);
                *(__nv_bfloat162*)(Lo + off0) =
                    __nv_bfloat162(__float2bfloat16(v0 - __bfloat162float(h0)),
                                   __float2bfloat16(v1 - __bfloat162float(h1)));
                *(__nv_bfloat162*)(Lo + off1) =
                    __nv_bfloat162(__float2bfloat16(v2 - __bfloat162float(h2)),
                                   __float2bfloat16(v3 - __bfloat162float(h3)));
            } else {
                __half h0 = __float2half_rn(v0), h1 = __float2half_rn(v1);
                __half h2 = __float2half_rn(v2), h3 = __float2half_rn(v3);
                __half* Hi = (__half*)oHi;
                __half* Lo = (__half*)oLo;
                *(__half2*)(Hi + off0) = __half2(h0, h1);
                *(__half2*)(Hi + off1) = __half2(h2, h3);
                *(__half2*)(Lo + off0) = __half2(__float2half_rn(v0 - __half2float(h0)),
                                                 __float2half_rn(v1 - __half2float(h1)));
                *(__half2*)(Lo + off1) = __half2(__float2half_rn(v2 - __half2float(h2)),
                                                 __float2half_rn(v3 - __half2float(h3)));
            }
        }
    }
}

__global__ __launch_bounds__(512, 1)
void gemm_qkv_tc(const float* __restrict__ bq, const float* __restrict__ bk,
                 const float* __restrict__ bv)
{
    const int z = blockIdx.z;
    if (z == 0)
        gemm_tc_body(g_xhi, g_xlo, g_wthi[0], g_wtlo[0], bq, nullptr, 1, g_qhi, g_qlo);
    else if (z == 1)
        gemm_tc_body(g_xhi, g_xlo, g_wthi[1], g_wtlo[1], bk, nullptr, 2, g_khi, g_klo);
    else
        gemm_tc_body(g_xhi, g_xlo, g_wthi[2], g_wtlo[2], bv, nullptr, 3, g_vhi, g_vlo);
}

__global__ __launch_bounds__(512, 1)
void gemm_out_tc(const float* __restrict__ bo, float* __restrict__ out)
{
    gemm_tc_body(g_aohi, g_aolo, g_wthi[3], g_wtlo[3], bo, out, 0, nullptr, nullptr);
}

// ---------------------------------------------------------------------------
// Tensor-core flash attention, causal, 2-stage cp.async K/V pipeline.
// CTA: 64 q rows, 128 threads. Output written pre-split bf16 hi/lo.
// ---------------------------------------------------------------------------
#define VPITCH 88
#define AQH 0
#define AQL 8192
#define AST 16384
#define SKH 0
#define SKL 8192
#define SVH 16384
#define SVL (16384 + 64 * VPITCH * 2)       // 27648
#define ASTAGE (SVL + 64 * VPITCH * 2)      // 38912
#define ATT_SMEM (AST + 2 * ASTAGE)         // 94208

__device__ __forceinline__ void attn_load_stage(uint32_t sb, int stage,
                                                const __nv_bfloat16* gkh,
                                                const __nv_bfloat16* gkl,
                                                const __half* gvh,
                                                const __half* gvl,
                                                int k0, int tid)
{
    uint32_t so = sb + AST + stage * ASTAGE;
#pragma unroll
    for (int i = 0; i < 4; i++) {
        int idx = tid + (i << 7);
        int r = idx >> 3, c = idx & 7;
        uint32_t offk = 128u * r + 16u * (c ^ (r & 7));
        size_t g = (size_t)(k0 + r) * DD + c * 8;
        cpasync16(so + SKH + offk, gkh + g);
        cpasync16(so + SKL + offk, gkl + g);
        uint32_t offv = (uint32_t)(r * VPITCH + c * 8) * 2;
        cpasync16(so + SVH + offv, gvh + g);
        cpasync16(so + SVL + offv, gvl + g);
    }
}

__global__ __launch_bounds__(128, 2) void attn_tc_kernel()
{
    extern __shared__ char sm[];
    const uint32_t sb = smem_to_u32(sm);
    const int tid = threadIdx.x;
    const int lane = tid & 31;
    const int wid = tid >> 5;
    const int bh = blockIdx.y;
    const int b = bh >> 4;
    const int h = bh & 15;
    const int q0 = (int)(gridDim.x - 1 - blockIdx.x) * 64;   // big tiles first

    const size_t tok0 = (size_t)(b * LL);
    const __nv_bfloat16* gqh = g_qhi + (tok0 + q0) * DD + h * 64;
    const __nv_bfloat16* gql = g_qlo + (tok0 + q0) * DD + h * 64;
    const __nv_bfloat16* gkh = g_khi + tok0 * DD + h * 64;
    const __nv_bfloat16* gkl = g_klo + tok0 * DD + h * 64;
    const __half*        gvh = g_vhi + tok0 * DD + h * 64;
    const __half*        gvl = g_vlo + tok0 * DD + h * 64;

    // kick off stage 0 loads immediately
    attn_load_stage(sb, 0, gkh, gkl, gvh, gvl, 0, tid);
    cpcommit();

    // V pad cols 64..87 in BOTH stages: zeros
#pragma unroll
    for (int s = 0; s < 2; s++) {
        char* vb = sm + AST + s * ASTAGE;
        for (int i = tid; i < 64 * 3; i += 128) {
            int r = i / 3, c = i % 3;
            uint32_t off = (uint32_t)(r * VPITCH + 64 + 8 * c) * 2;
            *(uint4*)(vb + SVH + off) = make_uint4(0, 0, 0, 0);
            *(uint4*)(vb + SVL + off) = make_uint4(0, 0, 0, 0);
        }
    }
    __syncthreads();   // zero-fill visible before ones-column write (R5 race fix)
#pragma unroll
    for (int s = 0; s < 2; s++) {
        char* vb = sm + AST + s * ASTAGE;
        if (tid < 64) ((__half*)(vb + SVH))[tid * VPITCH + 64] = __float2half(1.0f);
    }

    // Load Q tile (swizzled, regular loads)
#pragma unroll
    for (int i = 0; i < 4; i++) {
        int idx = tid + (i << 7);
        int r = idx >> 3, c = idx & 7;
        uint32_t off = 128u * r + 16u * (c ^ (r & 7));
        *(uint4*)(sm + AQH + off) = *(const uint4*)(gqh + (size_t)r * DD + c * 8);
        *(uint4*)(sm + AQL + off) = *(const uint4*)(gql + (size_t)r * DD + c * 8);
    }

    const int arow = 16 * wid + (lane & 15);
    const int ac = lane >> 4;
    const int asw = arow & 7;
    const int brow_in = ((lane >> 4) << 3) + (lane & 7);
    const int bc = (lane >> 3) & 1;
    const int bsw = brow_in & 7;
    const int vrow_in = (lane & 7) + ((lane >> 3) & 1) * 8;
    const int vnc = (lane >> 4);

    float oacc[9][4];
#pragma unroll
    for (int i = 0; i < 9; i++)
#pragma unroll
        for (int j = 0; j < 4; j++) oacc[i][j] = 0.f;
    float m2[2] = {-1e30f, -1e30f};

    const int nk = (q0 >> 6) + 1;
    for (int kt = 0; kt < nk; kt++) {
        if (kt + 1 < nk) {
            attn_load_stage(sb, (kt + 1) & 1, gkh, gkl, gvh, gvl, (kt + 1) * 64, tid);
            cpcommit();
            cpwait<1>();
        } else {
            cpwait<0>();
        }
        __syncthreads();
        const uint32_t st = sb + AST + (kt & 1) * ASTAGE;

        // ---- S = Q K^T (3-pass split bf16), 16x64 per warp ----
        float sacc[8][4];
#pragma unroll
        for (int i = 0; i < 8; i++)
#pragma unroll
            for (int j = 0; j < 4; j++) sacc[i][j] = 0.f;

#pragma unroll
        for (int ks = 0; ks < 4; ks++) {
            uint32_t qhf[4], qlf[4], kf[4][4];
            uint32_t ca = 16u * (uint32_t)((2 * ks + ac) ^ asw);
            ldsm4(qhf, sb + AQH + 128u * arow + ca);
            ldsm4(qlf, sb + AQL + 128u * arow + ca);
            uint32_t cb = 16u * (uint32_t)((2 * ks + bc) ^ bsw);
#pragma unroll
            for (int np = 0; np < 4; np++)
                ldsm4(kf[np], st + SKH + 128u * (16 * np + brow_in) + cb);
#pragma unroll
            for (int nt = 0; nt < 8; nt++) {
                mma_bf16(sacc[nt], qhf, &kf[nt >> 1][(nt & 1) * 2]);
                mma_bf16(sacc[nt], qlf, &kf[nt >> 1][(nt & 1) * 2]);
            }
#pragma unroll
            for (int np = 0; np < 4; np++)
                ldsm4(kf[np], st + SKL + 128u * (16 * np + brow_in) + cb);
#pragma unroll
            for (int nt = 0; nt < 8; nt++)
                mma_bf16(sacc[nt], qhf, &kf[nt >> 1][(nt & 1) * 2]);
        }

        // ---- causal mask (diagonal tile only) ----
        if (kt == nk - 1) {
            const int r0g = 16 * wid + (lane >> 2);
#pragma unroll
            for (int nt = 0; nt < 8; nt++) {
                int kc = 8 * nt + 2 * (lane & 3);
                if (kc > r0g)     sacc[nt][0] = -1e30f;
                if (kc + 1 > r0g) sacc[nt][1] = -1e30f;
                if (kc > r0g + 8)     sacc[nt][2] = -1e30f;
                if (kc + 1 > r0g + 8) sacc[nt][3] = -1e30f;
            }
        }

        // ---- online softmax (log2 domain), P in f16x2 ----
        float mx0 = -1e30f, mx1 = -1e30f;
#pragma unroll
        for (int nt = 0; nt < 8; nt++) {
            mx0 = fmaxf(mx0, fmaxf(sacc[nt][0], sacc[nt][1]));
            mx1 = fmaxf(mx1, fmaxf(sacc[nt][2], sacc[nt][3]));
        }
        mx0 = fmaxf(mx0, __shfl_xor_sync(0xffffffffu, mx0, 1));
        mx0 = fmaxf(mx0, __shfl_xor_sync(0xffffffffu, mx0, 2));
        mx1 = fmaxf(mx1, __shfl_xor_sync(0xffffffffu, mx1, 1));
        mx1 = fmaxf(mx1, __shfl_xor_sync(0xffffffffu, mx1, 2));
        float m2n0 = fmaxf(m2[0], mx0 * L2E);
        float m2n1 = fmaxf(m2[1], mx1 * L2E);
        float al0 = exp2f(m2[0] - m2n0);
        float al1 = exp2f(m2[1] - m2n1);
        m2[0] = m2n0; m2[1] = m2n1;

        uint32_t pf[4][4];
#pragma unroll
        for (int ks = 0; ks < 4; ks++) {
            pf[ks][0] = ex2_f16x2(cvt_f16x2(fmaf(sacc[2*ks][1],   L2E, -m2n0),
                                            fmaf(sacc[2*ks][0],   L2E, -m2n0)));
            pf[ks][1] = ex2_f16x2(cvt_f16x2(fmaf(sacc[2*ks][3],   L2E, -m2n1),
                                            fmaf(sacc[2*ks][2],   L2E, -m2n1)));
            pf[ks][2] = ex2_f16x2(cvt_f16x2(fmaf(sacc[2*ks+1][1], L2E, -m2n0),
                                            fmaf(sacc[2*ks+1][0], L2E, -m2n0)));
            pf[ks][3] = ex2_f16x2(cvt_f16x2(fmaf(sacc[2*ks+1][3], L2E, -m2n1),
                                            fmaf(sacc[2*ks+1][2], L2E, -m2n1)));
        }
#pragma unroll
        for (int nt = 0; nt < 9; nt++) {
            oacc[nt][0] *= al0; oacc[nt][1] *= al0;
            oacc[nt][2] *= al1; oacc[nt][3] *= al1;
        }

        // ---- O += P @ V (f16, V hi/lo 2-pass; n=72 incl. ones column) ----
#pragma unroll
        for (int ks = 0; ks < 4; ks++) {
            const uint32_t vrow = (uint32_t)(16 * ks + vrow_in) * (VPITCH * 2);
#pragma unroll
            for (int np = 0; np < 5; np++) {
                uint32_t vf[4];
                uint32_t voff = vrow + 16u * (uint32_t)(2 * np + vnc);
                ldsm4t(vf, st + SVH + voff);
                mma_f16(oacc[2 * np], pf[ks], &vf[0]);
                if (np < 4) mma_f16(oacc[2 * np + 1], pf[ks], &vf[2]);
            }
#pragma unroll
            for (int np = 0; np < 5; np++) {
                uint32_t vf[4];
                uint32_t voff = vrow + 16u * (uint32_t)(2 * np + vnc);
                ldsm4t(vf, st + SVL + voff);
                mma_f16(oacc[2 * np], pf[ks], &vf[0]);
                if (np < 4) mma_f16(oacc[2 * np + 1], pf[ks], &vf[2]);
            }
        }
        __syncthreads();
    }

    // ---- normalize and store pre-split bf16 hi/lo ----
    const int src = lane & ~3;
    float l0 = __shfl_sync(0xffffffffu, oacc[8][0], src);
    float l1 = __shfl_sync(0xffffffffu, oacc[8][2], src);
    float i0 = 1.0f / l0;
    float i1 = 1.0f / l1;
    const int row0 = q0 + 16 * wid + (lane >> 2);
    __nv_bfloat16* baseh = g_aohi + tok0 * DD + h * 64;
    __nv_bfloat16* basel = g_aolo + tok0 * DD + h * 64;
#pragma unroll
    for (int nt = 0; nt < 8; nt++) {
        int col = 8 * nt + 2 * (lane & 3);
        float v0 = oacc[nt][0] * i0, v1 = oacc[nt][1] * i0;
        float v2 = oacc[nt][2] * i1, v3 = oacc[nt][3] * i1;
        __nv_bfloat16 h0 = __float2bfloat16(v0), h1 = __float2bfloat16(v1);
        __nv_bfloat16 h2 = __float2bfloat16(v2), h3 = __float2bfloat16(v3);
        size_t off0 = (size_t)row0 * DD + col;
        size_t off1 = (size_t)(row0 + 8) * DD + col;
        *(__nv_bfloat162*)(baseh + off0) = __nv_bfloat162(h0, h1);
        *(__nv_bfloat162*)(baseh + off1) = __nv_bfloat162(h2, h3);
        *(__nv_bfloat162*)(basel + off0) =
            __nv_bfloat162(__float2bfloat16(v0 - __bfloat162float(h0)),
                           __float2bfloat16(v1 - __bfloat162float(h1)));
        *(__nv_bfloat162*)(basel + off1) =
            __nv_bfloat162(__float2bfloat16(v2 - __bfloat162float(h2)),
                           __float2bfloat16(v3 - __bfloat162float(h3)));
    }
}

// ---------------------------------------------------------------------------
extern "C" void kernel_launch(void* const* d_in, const int* in_sizes, int n_in,
                              void* d_out, int out_size)
{
    (void)in_sizes; (void)n_in; (void)out_size;
    const float* x  = (const float*)d_in[0];
    const float* wq = (const float*)d_in[2];
    const float* bq = (const float*)d_in[3];
    const float* wk = (const float*)d_in[4];
    const float* bk = (const float*)d_in[5];
    const float* wv = (const float*)d_in[6];
    const float* bv = (const float*)d_in[7];
    const float* wo = (const float*)d_in[8];
    const float* bo = (const float*)d_in[9];
    float* out = (float*)d_out;

    cudaFuncSetAttribute(gemm_qkv_tc, cudaFuncAttributeMaxDynamicSharedMemorySize,
                         GEMM_SMEM_BYTES);
    cudaFuncSetAttribute(gemm_out_tc, cudaFuncAttributeMaxDynamicSharedMemorySize,
                         GEMM_SMEM_BYTES);
    cudaFuncSetAttribute(attn_tc_kernel, cudaFuncAttributeMaxDynamicSharedMemorySize,
                         ATT_SMEM);

    split_kernel<<<(MM * DD / 4) / 256, 256>>>(x);
    wsplit_kernel<<<dim3(32, 32, 4), dim3(32, 32)>>>(wq, wk, wv, wo);
    gemm_qkv_tc<<<dim3(DD / 128, MM / 128, 3), 512, GEMM_SMEM_BYTES>>>(bq, bk, bv);
    attn_tc_kernel<<<dim3(LL / 64, BB * HH), 128, ATT_SMEM>>>();
    gemm_out_tc<<<dim3(DD / 128, MM / 128), 512, GEMM_SMEM_BYTES>>>(bo, out);
}

// round 7
// speedup vs baseline: 1.7561x; 1.7561x over previous
#include <cuda_runtime.h>
#include <cuda_bf16.h>
#include <cuda_fp16.h>
#include <cstdint>
#include <math.h>

#define BB 2
#define LL 2048
#define DD 1024
#define HH 16
#define DHH 64
#define MM (BB * LL)   // 4096
#define L2E 1.4426950408889634f

// ---------------------------------------------------------------------------
// Scratch (__device__ globals: allocation-free rule)
// ---------------------------------------------------------------------------
__device__ __half g_x16[MM * DD];        // x in fp16
__device__ __half g_ao16[MM * DD];       // attention output in fp16
__device__ __half g_wt16[4][DD * DD];    // transposed weights [which][n][k] fp16

// attention operands, pre-split by the projection epilogues
__device__ __nv_bfloat16 g_qhi[MM * DD];  // pre-scaled by 0.125
__device__ __nv_bfloat16 g_qlo[MM * DD];
__device__ __nv_bfloat16 g_khi[MM * DD];
__device__ __nv_bfloat16 g_klo[MM * DD];
__device__ __half        g_vhi[MM * DD];
__device__ __half        g_vlo[MM * DD];

// ---------------------------------------------------------------------------
// PTX helpers (portable sm_80+ subset; plain sm_103 target — no tcgen05)
// ---------------------------------------------------------------------------
__device__ __forceinline__ uint32_t smem_to_u32(const void* p) {
    uint32_t a;
    asm("{ .reg .u64 t; cvta.to.shared.u64 t, %1; cvt.u32.u64 %0, t; }"
        : "=r"(a) : "l"(p));
    return a;
}
__device__ __forceinline__ void cpasync16(uint32_t s, const void* g) {
    asm volatile("cp.async.cg.shared.global [%0], [%1], 16;" :: "r"(s), "l"(g));
}
__device__ __forceinline__ void cpcommit() {
    asm volatile("cp.async.commit_group;" ::: "memory");
}
template <int N>
__device__ __forceinline__ void cpwait() {
    asm volatile("cp.async.wait_group %0;" :: "n"(N) : "memory");
}
__device__ __forceinline__ void ldsm4(uint32_t* r, uint32_t addr) {
    asm volatile("ldmatrix.sync.aligned.m8n8.x4.shared.b16 {%0,%1,%2,%3}, [%4];"
                 : "=r"(r[0]), "=r"(r[1]), "=r"(r[2]), "=r"(r[3]) : "r"(addr));
}
__device__ __forceinline__ void ldsm4t(uint32_t* r, uint32_t addr) {
    asm volatile("ldmatrix.sync.aligned.m8n8.x4.trans.shared.b16 {%0,%1,%2,%3}, [%4];"
                 : "=r"(r[0]), "=r"(r[1]), "=r"(r[2]), "=r"(r[3]) : "r"(addr));
}
__device__ __forceinline__ void mma_bf16(float* d, const uint32_t* a, const uint32_t* b) {
    asm volatile(
        "mma.sync.aligned.m16n8k16.row.col.f32.bf16.bf16.f32 "
        "{%0,%1,%2,%3}, {%4,%5,%6,%7}, {%8,%9}, {%0,%1,%2,%3};"
        : "+f"(d[0]), "+f"(d[1]), "+f"(d[2]), "+f"(d[3])
        : "r"(a[0]), "r"(a[1]), "r"(a[2]), "r"(a[3]), "r"(b[0]), "r"(b[1]));
}
__device__ __forceinline__ void mma_f16(float* d, const uint32_t* a, const uint32_t* b) {
    asm volatile(
        "mma.sync.aligned.m16n8k16.row.col.f32.f16.f16.f32 "
        "{%0,%1,%2,%3}, {%4,%5,%6,%7}, {%8,%9}, {%0,%1,%2,%3};"
        : "+f"(d[0]), "+f"(d[1]), "+f"(d[2]), "+f"(d[3])
        : "r"(a[0]), "r"(a[1]), "r"(a[2]), "r"(a[3]), "r"(b[0]), "r"(b[1]));
}
__device__ __forceinline__ uint32_t cvt_f16x2(float hi, float lo) {
    uint32_t r;
    asm volatile("cvt.rn.f16x2.f32 %0, %1, %2;" : "=r"(r) : "f"(hi), "f"(lo));
    return r;
}
__device__ __forceinline__ uint32_t ex2_f16x2(uint32_t x) {
    uint32_t r;
    asm volatile("ex2.approx.f16x2 %0, %1;" : "=r"(r) : "r"(x));
    return r;
}

// ---------------------------------------------------------------------------
// Prep kernels
// ---------------------------------------------------------------------------
__global__ __launch_bounds__(256) void xconv_kernel(const float* __restrict__ in)
{
    int i = blockIdx.x * blockDim.x + threadIdx.x;
    float4 v = ((const float4*)in)[i];
    __half2* hp = (__half2*)g_x16;
    hp[2 * i]     = __floats2half2_rn(v.x, v.y);
    hp[2 * i + 1] = __floats2half2_rn(v.z, v.w);
}

// Transpose weights: W[K][N] -> Wt[n][k] fp16
__global__ __launch_bounds__(1024) void wconv_kernel(const float* __restrict__ wq,
                                                     const float* __restrict__ wk,
                                                     const float* __restrict__ wv,
                                                     const float* __restrict__ wo)
{
    __shared__ float t[32][33];
    int which = blockIdx.z;
    const float* w = (which == 0) ? wq : (which == 1) ? wk : (which == 2) ? wv : wo;
    int kk = blockIdx.y * 32 + threadIdx.y;
    int nn = blockIdx.x * 32 + threadIdx.x;
    t[threadIdx.y][threadIdx.x] = w[kk * DD + nn];
    __syncthreads();
    int on = blockIdx.x * 32 + threadIdx.y;
    int ok = blockIdx.y * 32 + threadIdx.x;
    g_wt16[which][on * DD + ok] = __float2half_rn(t[threadIdx.x][threadIdx.y]);
}

// ---------------------------------------------------------------------------
// Single-pass fp16 HMMA GEMM: C[128,128 tile] = A @ Wt^T + bias
// 256 threads, warp grid 2(m)x4(n), warp tile 64x32, BK=32, 3-stage cp.async.
// mode 0: fp32 C; 1: bf16 split *0.125 (Q); 2: bf16 split (K); 3: f16 split (V)
// ---------------------------------------------------------------------------
#define BK 32
#define APITCH 40
#define BUF_BYTES (128 * APITCH * 2)        // 10240 per operand buffer
#define GEMM_STAGE (2 * BUF_BYTES)          // 20480 (A + B)
#define GEMM_SMEM_BYTES (3 * GEMM_STAGE)    // 61440

__device__ __forceinline__ void load_stage(uint32_t sbase, int stage,
                                           const __half* __restrict__ A,
                                           const __half* __restrict__ B,
                                           int m0, int n0, int k0, int tid)
{
    uint32_t so = sbase + stage * GEMM_STAGE;
#pragma unroll
    for (int j = 0; j < 2; j++) {
        int c = tid + (j << 8);                 // 0..511
        int row = c >> 2;                       // 0..127
        int col = (c & 3) << 3;                 // 0,8,16,24
        uint32_t soff = (uint32_t)(row * APITCH + col) * 2;
        cpasync16(so + 0 * BUF_BYTES + soff, A + (size_t)(m0 + row) * DD + k0 + col);
        cpasync16(so + 1 * BUF_BYTES + soff, B + (size_t)(n0 + row) * DD + k0 + col);
    }
}

__device__ __forceinline__ void gemm_tc_body(const __half* __restrict__ A,
                                             const __half* __restrict__ B,
                                             const float* __restrict__ bias,
                                             float* __restrict__ C,
                                             int mode, void* oHi, void* oLo)
{
    extern __shared__ char smem[];
    const uint32_t sbase = smem_to_u32(smem);

    const int tid = threadIdx.x;
    const int lane = tid & 31;
    const int wid = tid >> 5;
    const int wm = (wid >> 2) * 64;     // 0 or 64
    const int wn = (wid & 3) * 32;      // 0,32,64,96
    const int m0 = blockIdx.y * 128;
    const int n0 = blockIdx.x * 128;

    const int a_row = wm + (lane & 15);
    const int a_col = (lane >> 4) << 3;
    const int b_row = wn + ((lane >> 4) << 3) + (lane & 7);
    const int b_col = ((lane >> 3) & 1) << 3;

    float acc[4][4][4];
#pragma unroll
    for (int i = 0; i < 4; i++)
#pragma unroll
        for (int j = 0; j < 4; j++)
#pragma unroll
            for (int r = 0; r < 4; r++) acc[i][j][r] = 0.f;

    load_stage(sbase, 0, A, B, m0, n0, 0, tid);
    cpcommit();
    load_stage(sbase, 1, A, B, m0, n0, BK, tid);
    cpcommit();

    const int NT = DD / BK;             // 32
    int st_idx = 0;
    for (int kt = 0; kt < NT; kt++) {
        if (kt + 2 < NT) {
            int ps = st_idx + 2; if (ps >= 3) ps -= 3;
            load_stage(sbase, ps, A, B, m0, n0, (kt + 2) * BK, tid);
            cpcommit();
            cpwait<2>();
        } else if (kt + 1 < NT) {
            cpwait<1>();
        } else {
            cpwait<0>();
        }
        __syncthreads();

        const uint32_t st = sbase + st_idx * GEMM_STAGE;
#pragma unroll
        for (int ks = 0; ks < 2; ks++) {
            const int kofs = ks * 16;
            uint32_t ah[4][4], bh[2][4];
#pragma unroll
            for (int mt = 0; mt < 4; mt++) {
                uint32_t off = (uint32_t)((a_row + mt * 16) * APITCH + kofs + a_col) * 2;
                ldsm4(ah[mt], st + 0 * BUF_BYTES + off);
            }
#pragma unroll
            for (int nt2 = 0; nt2 < 2; nt2++) {
                uint32_t off = (uint32_t)((b_row + nt2 * 16) * APITCH + kofs + b_col) * 2;
                ldsm4(bh[nt2], st + 1 * BUF_BYTES + off);
            }
#pragma unroll
            for (int mt = 0; mt < 4; mt++)
#pragma unroll
                for (int nt = 0; nt < 4; nt++)
                    mma_f16(acc[mt][nt], ah[mt], &bh[nt >> 1][(nt & 1) * 2]);
        }
        __syncthreads();
        if (++st_idx == 3) st_idx = 0;
    }

    const float sc = (mode == 1) ? 0.125f : 1.0f;
#pragma unroll
    for (int mt = 0; mt < 4; mt++) {
        int row = m0 + wm + mt * 16 + (lane >> 2);
#pragma unroll
        for (int nt = 0; nt < 4; nt++) {
            int col = n0 + wn + nt * 8 + 2 * (lane & 3);
            float b0 = bias[col], b1 = bias[col + 1];
            float v0 = acc[mt][nt][0] + b0, v1 = acc[mt][nt][1] + b1;
            float v2 = acc[mt][nt][2] + b0, v3 = acc[mt][nt][3] + b1;
            size_t off0 = (size_t)row * DD + col;
            size_t off1 = (size_t)(row + 8) * DD + col;
            if (mode == 0) {
                *(float2*)(C + off0) = make_float2(v0, v1);
                *(float2*)(C + off1) = make_float2(v2, v3);
            } else if (mode <= 2) {
                v0 *= sc; v1 *= sc; v2 *= sc; v3 *= sc;
                __nv_bfloat16 h0 = __float2bfloat16(v0), h1 = __float2bfloat16(v1);
                __nv_bfloat16 h2 = __float2bfloat16(v2), h3 = __float2bfloat16(v3);
                __nv_bfloat16* Hi = (__nv_bfloat16*)oHi;
                __nv_bfloat16* Lo = (__nv_bfloat16*)oLo;
                *(__nv_bfloat162*)(Hi + off0) = __nv_bfloat162(h0, h1);
                *(__nv_bfloat162*)(Hi + off1) = __nv_bfloat162(h2, h3);
                *(__nv_bfloat162*)(Lo + off0) =
                    __nv_bfloat162(__float2bfloat16(v0 - __bfloat162float(h0)),
                                   __float2bfloat16(v1 - __bfloat162float(h1)));
                *(__nv_bfloat162*)(Lo + off1) =
                    __nv_bfloat162(__float2bfloat16(v2 - __bfloat162float(h2)),
                                   __float2bfloat16(v3 - __bfloat162float(h3)));
            } else {
                __half h0 = __float2half_rn(v0), h1 = __float2half_rn(v1);
                __half h2 = __float2half_rn(v2), h3 = __float2half_rn(v3);
                __half* Hi = (__half*)oHi;
                __half* Lo = (__half*)oLo;
                *(__half2*)(Hi + off0) = __half2(h0, h1);
                *(__half2*)(Hi + off1) = __half2(h2, h3);
                *(__half2*)(Lo + off0) = __half2(__float2half_rn(v0 - __half2float(h0)),
                                                 __float2half_rn(v1 - __half2float(h1)));
                *(__half2*)(Lo + off1) = __half2(__float2half_rn(v2 - __half2float(h2)),
                                                 __float2half_rn(v3 - __half2float(h3)));
            }
        }
    }
}

__global__ __launch_bounds__(256, 2)
void gemm_qkv_tc(const float* __restrict__ bq, const float* __restrict__ bk,
                 const float* __restrict__ bv)
{
    const int z = blockIdx.z;
    if (z == 0)
        gemm_tc_body(g_x16, g_wt16[0], bq, nullptr, 1, g_qhi, g_qlo);
    else if (z == 1)
        gemm_tc_body(g_x16, g_wt16[1], bk, nullptr, 2, g_khi, g_klo);
    else
        gemm_tc_body(g_x16, g_wt16[2], bv, nullptr, 3, g_vhi, g_vlo);
}

__global__ __launch_bounds__(256, 2)
void gemm_out_tc(const float* __restrict__ bo, float* __restrict__ out)
{
    gemm_tc_body(g_ao16, g_wt16[3], bo, out, 0, nullptr, nullptr);
}

// ---------------------------------------------------------------------------
// Tensor-core flash attention, causal, 2-stage cp.async K/V pipeline.
// CTA: 64 q rows, 128 threads. Output written fp16 (out-proj operand).
// ---------------------------------------------------------------------------
#define VPITCH 88
#define AQH 0
#define AQL 8192
#define AST 16384
#define SKH 0
#define SKL 8192
#define SVH 16384
#define SVL (16384 + 64 * VPITCH * 2)       // 27648
#define ASTAGE (SVL + 64 * VPITCH * 2)      // 38912
#define ATT_SMEM (AST + 2 * ASTAGE)         // 94208

__device__ __forceinline__ void attn_load_stage(uint32_t sb, int stage,
                                                const __nv_bfloat16* gkh,
                                                const __nv_bfloat16* gkl,
                                                const __half* gvh,
                                                const __half* gvl,
                                                int k0, int tid)
{
    uint32_t so = sb + AST + stage * ASTAGE;
#pragma unroll
    for (int i = 0; i < 4; i++) {
        int idx = tid + (i << 7);
        int r = idx >> 3, c = idx & 7;
        uint32_t offk = 128u * r + 16u * (c ^ (r & 7));
        size_t g = (size_t)(k0 + r) * DD + c * 8;
        cpasync16(so + SKH + offk, gkh + g);
        cpasync16(so + SKL + offk, gkl + g);
        uint32_t offv = (uint32_t)(r * VPITCH + c * 8) * 2;
        cpasync16(so + SVH + offv, gvh + g);
        cpasync16(so + SVL + offv, gvl + g);
    }
}

__global__ __launch_bounds__(128, 2) void attn_tc_kernel()
{
    extern __shared__ char sm[];
    const uint32_t sb = smem_to_u32(sm);
    const int tid = threadIdx.x;
    const int lane = tid & 31;
    const int wid = tid >> 5;
    const int bh = blockIdx.y;
    const int b = bh >> 4;
    const int h = bh & 15;
    const int q0 = (int)(gridDim.x - 1 - blockIdx.x) * 64;   // big tiles first

    const size_t tok0 = (size_t)(b * LL);
    const __nv_bfloat16* gqh = g_qhi + (tok0 + q0) * DD + h * 64;
    const __nv_bfloat16* gql = g_qlo + (tok0 + q0) * DD + h * 64;
    const __nv_bfloat16* gkh = g_khi + tok0 * DD + h * 64;
    const __nv_bfloat16* gkl = g_klo + tok0 * DD + h * 64;
    const __half*        gvh = g_vhi + tok0 * DD + h * 64;
    const __half*        gvl = g_vlo + tok0 * DD + h * 64;

    // kick off stage 0 loads immediately
    attn_load_stage(sb, 0, gkh, gkl, gvh, gvl, 0, tid);
    cpcommit();

    // V pad cols 64..87 in BOTH stages: zeros
#pragma unroll
    for (int s = 0; s < 2; s++) {
        char* vb = sm + AST + s * ASTAGE;
        for (int i = tid; i < 64 * 3; i += 128) {
            int r = i / 3, c = i % 3;
            uint32_t off = (uint32_t)(r * VPITCH + 64 + 8 * c) * 2;
            *(uint4*)(vb + SVH + off) = make_uint4(0, 0, 0, 0);
            *(uint4*)(vb + SVL + off) = make_uint4(0, 0, 0, 0);
        }
    }
    __syncthreads();   // zero-fill visible before ones-column write
#pragma unroll
    for (int s = 0; s < 2; s++) {
        char* vb = sm + AST + s * ASTAGE;
        if (tid < 64) ((__half*)(vb + SVH))[tid * VPITCH + 64] = __float2half(1.0f);
    }

    // Load Q tile (swizzled, regular loads)
#pragma unroll
    for (int i = 0; i < 4; i++) {
        int idx = tid + (i << 7);
        int r = idx >> 3, c = idx & 7;
        uint32_t off = 128u * r + 16u * (c ^ (r & 7));
        *(uint4*)(sm + AQH + off) = *(const uint4*)(gqh + (size_t)r * DD + c * 8);
        *(uint4*)(sm + AQL + off) = *(const uint4*)(gql + (size_t)r * DD + c * 8);
    }

    const int arow = 16 * wid + (lane & 15);
    const int ac = lane >> 4;
    const int asw = arow & 7;
    const int brow_in = ((lane >> 4) << 3) + (lane & 7);
    const int bc = (lane >> 3) & 1;
    const int bsw = brow_in & 7;
    const int vrow_in = (lane & 7) + ((lane >> 3) & 1) * 8;
    const int vnc = (lane >> 4);

    float oacc[9][4];
#pragma unroll
    for (int i = 0; i < 9; i++)
#pragma unroll
        for (int j = 0; j < 4; j++) oacc[i][j] = 0.f;
    float m2[2] = {-1e30f, -1e30f};

    const int nk = (q0 >> 6) + 1;
    for (int kt = 0; kt < nk; kt++) {
        if (kt + 1 < nk) {
            attn_load_stage(sb, (kt + 1) & 1, gkh, gkl, gvh, gvl, (kt + 1) * 64, tid);
            cpcommit();
            cpwait<1>();
        } else {
            cpwait<0>();
        }
        __syncthreads();
        const uint32_t st = sb + AST + (kt & 1) * ASTAGE;

        // ---- S = Q K^T (3-pass split bf16), 16x64 per warp ----
        float sacc[8][4];
#pragma unroll
        for (int i = 0; i < 8; i++)
#pragma unroll
            for (int j = 0; j < 4; j++) sacc[i][j] = 0.f;

#pragma unroll
        for (int ks = 0; ks < 4; ks++) {
            uint32_t qhf[4], qlf[4], kf[4][4];
            uint32_t ca = 16u * (uint32_t)((2 * ks + ac) ^ asw);
            ldsm4(qhf, sb + AQH + 128u * arow + ca);
            ldsm4(qlf, sb + AQL + 128u * arow + ca);
            uint32_t cb = 16u * (uint32_t)((2 * ks + bc) ^ bsw);
#pragma unroll
            for (int np = 0; np < 4; np++)
                ldsm4(kf[np], st + SKH + 128u * (16 * np + brow_in) + cb);
#pragma unroll
            for (int nt = 0; nt < 8; nt++) {
                mma_bf16(sacc[nt], qhf, &kf[nt >> 1][(nt & 1) * 2]);
                mma_bf16(sacc[nt], qlf, &kf[nt >> 1][(nt & 1) * 2]);
            }
#pragma unroll
            for (int np = 0; np < 4; np++)
                ldsm4(kf[np], st + SKL + 128u * (16 * np + brow_in) + cb);
#pragma unroll
            for (int nt = 0; nt < 8; nt++)
                mma_bf16(sacc[nt], qhf, &kf[nt >> 1][(nt & 1) * 2]);
        }

        // ---- causal mask (diagonal tile only) ----
        if (kt == nk - 1) {
            const int r0g = 16 * wid + (lane >> 2);
#pragma unroll
            for (int nt = 0; nt < 8; nt++) {
                int kc = 8 * nt + 2 * (lane & 3);
                if (kc > r0g)     sacc[nt][0] = -1e30f;
                if (kc + 1 > r0g) sacc[nt][1] = -1e30f;
                if (kc > r0g + 8)     sacc[nt][2] = -1e30f;
                if (kc + 1 > r0g + 8) sacc[nt][3] = -1e30f;
            }
        }

        // ---- online softmax (log2 domain), P in f16x2 ----
        float mx0 = -1e30f, mx1 = -1e30f;
#pragma unroll
        for (int nt = 0; nt < 8; nt++) {
            mx0 = fmaxf(mx0, fmaxf(sacc[nt][0], sacc[nt][1]));
            mx1 = fmaxf(mx1, fmaxf(sacc[nt][2], sacc[nt][3]));
        }
        mx0 = fmaxf(mx0, __shfl_xor_sync(0xffffffffu, mx0, 1));
        mx0 = fmaxf(mx0, __shfl_xor_sync(0xffffffffu, mx0, 2));
        mx1 = fmaxf(mx1, __shfl_xor_sync(0xffffffffu, mx1, 1));
        mx1 = fmaxf(mx1, __shfl_xor_sync(0xffffffffu, mx1, 2));
        float m2n0 = fmaxf(m2[0], mx0 * L2E);
        float m2n1 = fmaxf(m2[1], mx1 * L2E);
        float al0 = exp2f(m2[0] - m2n0);
        float al1 = exp2f(m2[1] - m2n1);
        m2[0] = m2n0; m2[1] = m2n1;

        uint32_t pf[4][4];
#pragma unroll
        for (int ks = 0; ks < 4; ks++) {
            pf[ks][0] = ex2_f16x2(cvt_f16x2(fmaf(sacc[2*ks][1],   L2E, -m2n0),
                                            fmaf(sacc[2*ks][0],   L2E, -m2n0)));
            pf[ks][1] = ex2_f16x2(cvt_f16x2(fmaf(sacc[2*ks][3],   L2E, -m2n1),
                                            fmaf(sacc[2*ks][2],   L2E, -m2n1)));
            pf[ks][2] = ex2_f16x2(cvt_f16x2(fmaf(sacc[2*ks+1][1], L2E, -m2n0),
                                            fmaf(sacc[2*ks+1][0], L2E, -m2n0)));
            pf[ks][3] = ex2_f16x2(cvt_f16x2(fmaf(sacc[2*ks+1][3], L2E, -m2n1),
                                            fmaf(sacc[2*ks+1][2], L2E, -m2n1)));
        }
#pragma unroll
        for (int nt = 0; nt < 9; nt++) {
            oacc[nt][0] *= al0; oacc[nt][1] *= al0;
            oacc[nt][2] *= al1; oacc[nt][3] *= al1;
        }

        // ---- O += P @ V (f16, V hi/lo 2-pass; n=72 incl. ones column) ----
#pragma unroll
        for (int ks = 0; ks < 4; ks++) {
            const uint32_t vrow = (uint32_t)(16 * ks + vrow_in) * (VPITCH * 2);
#pragma unroll
            for (int np = 0; np < 5; np++) {
                uint32_t vf[4];
                uint32_t voff = vrow + 16u * (uint32_t)(2 * np + vnc);
                ldsm4t(vf, st + SVH + voff);
                mma_f16(oacc[2 * np], pf[ks], &vf[0]);
                if (np < 4) mma_f16(oacc[2 * np + 1], pf[ks], &vf[2]);
            }
#pragma unroll
            for (int np = 0; np < 5; np++) {
                uint32_t vf[4];
                uint32_t voff = vrow + 16u * (uint32_t)(2 * np + vnc);
                ldsm4t(vf, st + SVL + voff);
                mma_f16(oacc[2 * np], pf[ks], &vf[0]);
                if (np < 4) mma_f16(oacc[2 * np + 1], pf[ks], &vf[2]);
            }
        }
        __syncthreads();
    }

    // ---- normalize and store fp16 (out-proj operand) ----
    const int src = lane & ~3;
    float l0 = __shfl_sync(0xffffffffu, oacc[8][0], src);
    float l1 = __shfl_sync(0xffffffffu, oacc[8][2], src);
    float i0 = 1.0f / l0;
    float i1 = 1.0f / l1;
    const int row0 = q0 + 16 * wid + (lane >> 2);
    __half* base16 = g_ao16 + tok0 * DD + h * 64;
#pragma unroll
    for (int nt = 0; nt < 8; nt++) {
        int col = 8 * nt + 2 * (lane & 3);
        size_t off0 = (size_t)row0 * DD + col;
        size_t off1 = (size_t)(row0 + 8) * DD + col;
        *(__half2*)(base16 + off0) = __floats2half2_rn(oacc[nt][0] * i0, oacc[nt][1] * i0);
        *(__half2*)(base16 + off1) = __floats2half2_rn(oacc[nt][2] * i1, oacc[nt][3] * i1);
    }
}

// ---------------------------------------------------------------------------
extern "C" void kernel_launch(void* const* d_in, const int* in_sizes, int n_in,
                              void* d_out, int out_size)
{
    (void)in_sizes; (void)n_in; (void)out_size;
    const float* x  = (const float*)d_in[0];
    const float* wq = (const float*)d_in[2];
    const float* bq = (const float*)d_in[3];
    const float* wk = (const float*)d_in[4];
    const float* bk = (const float*)d_in[5];
    const float* wv = (const float*)d_in[6];
    const float* bv = (const float*)d_in[7];
    const float* wo = (const float*)d_in[8];
    const float* bo = (const float*)d_in[9];
    float* out = (float*)d_out;

    cudaFuncSetAttribute(gemm_qkv_tc, cudaFuncAttributeMaxDynamicSharedMemorySize,
                         GEMM_SMEM_BYTES);
    cudaFuncSetAttribute(gemm_out_tc, cudaFuncAttributeMaxDynamicSharedMemorySize,
                         GEMM_SMEM_BYTES);
    cudaFuncSetAttribute(attn_tc_kernel, cudaFuncAttributeMaxDynamicSharedMemorySize,
                         ATT_SMEM);

    xconv_kernel<<<(MM * DD / 4) / 256, 256>>>(x);
    wconv_kernel<<<dim3(32, 32, 4), dim3(32, 32)>>>(wq, wk, wv, wo);
    gemm_qkv_tc<<<dim3(DD / 128, MM / 128, 3), 256, GEMM_SMEM_BYTES>>>(bq, bk, bv);
    attn_tc_kernel<<<dim3(LL / 64, BB * HH), 128, ATT_SMEM>>>();
    gemm_out_tc<<<dim3(DD / 128, MM / 128), 256, GEMM_SMEM_BYTES>>>(bo, out);
}

// round 8
// speedup vs baseline: 2.3248x; 1.3238x over previous
#include <cuda_runtime.h>
#include <cuda_bf16.h>
#include <cuda_fp16.h>
#include <cstdint>
#include <math.h>

#define BB 2
#define LL 2048
#define DD 1024
#define HH 16
#define DHH 64
#define MM (BB * LL)   // 4096
#define L2E 1.4426950408889634f

// ---------------------------------------------------------------------------
// Scratch (__device__ globals: allocation-free rule)
// ---------------------------------------------------------------------------
__device__ __half g_x16[MM * DD];        // x in fp16
__device__ __half g_ao16[MM * DD];       // attention output in fp16
__device__ __half g_wt16[4][DD * DD];    // transposed weights [which][n][k] fp16

__device__ __half g_q16[MM * DD];        // Q fp16, pre-scaled by 0.125
__device__ __half g_k16[MM * DD];        // K fp16
__device__ __half g_v16[MM * DD];        // V fp16

// ---------------------------------------------------------------------------
// PTX helpers (portable sm_80+ subset; plain sm_103 target — no tcgen05)
// ---------------------------------------------------------------------------
__device__ __forceinline__ uint32_t smem_to_u32(const void* p) {
    uint32_t a;
    asm("{ .reg .u64 t; cvta.to.shared.u64 t, %1; cvt.u32.u64 %0, t; }"
        : "=r"(a) : "l"(p));
    return a;
}
__device__ __forceinline__ void cpasync16(uint32_t s, const void* g) {
    asm volatile("cp.async.cg.shared.global [%0], [%1], 16;" :: "r"(s), "l"(g));
}
__device__ __forceinline__ void cpcommit() {
    asm volatile("cp.async.commit_group;" ::: "memory");
}
template <int N>
__device__ __forceinline__ void cpwait() {
    asm volatile("cp.async.wait_group %0;" :: "n"(N) : "memory");
}
__device__ __forceinline__ void ldsm4(uint32_t* r, uint32_t addr) {
    asm volatile("ldmatrix.sync.aligned.m8n8.x4.shared.b16 {%0,%1,%2,%3}, [%4];"
                 : "=r"(r[0]), "=r"(r[1]), "=r"(r[2]), "=r"(r[3]) : "r"(addr));
}
__device__ __forceinline__ void ldsm4t(uint32_t* r, uint32_t addr) {
    asm volatile("ldmatrix.sync.aligned.m8n8.x4.trans.shared.b16 {%0,%1,%2,%3}, [%4];"
                 : "=r"(r[0]), "=r"(r[1]), "=r"(r[2]), "=r"(r[3]) : "r"(addr));
}
__device__ __forceinline__ void mma_f16(float* d, const uint32_t* a, const uint32_t* b) {
    asm volatile(
        "mma.sync.aligned.m16n8k16.row.col.f32.f16.f16.f32 "
        "{%0,%1,%2,%3}, {%4,%5,%6,%7}, {%8,%9}, {%0,%1,%2,%3};"
        : "+f"(d[0]), "+f"(d[1]), "+f"(d[2]), "+f"(d[3])
        : "r"(a[0]), "r"(a[1]), "r"(a[2]), "r"(a[3]), "r"(b[0]), "r"(b[1]));
}
__device__ __forceinline__ uint32_t cvt_f16x2(float hi, float lo) {
    uint32_t r;
    asm volatile("cvt.rn.f16x2.f32 %0, %1, %2;" : "=r"(r) : "f"(hi), "f"(lo));
    return r;
}
__device__ __forceinline__ uint32_t ex2_f16x2(uint32_t x) {
    uint32_t r;
    asm volatile("ex2.approx.f16x2 %0, %1;" : "=r"(r) : "r"(x));
    return r;
}

// ---------------------------------------------------------------------------
// Prep kernels
// ---------------------------------------------------------------------------
__global__ __launch_bounds__(256) void xconv_kernel(const float* __restrict__ in)
{
    int i = blockIdx.x * blockDim.x + threadIdx.x;
    float4 v = ((const float4*)in)[i];
    __half2* hp = (__half2*)g_x16;
    hp[2 * i]     = __floats2half2_rn(v.x, v.y);
    hp[2 * i + 1] = __floats2half2_rn(v.z, v.w);
}

// Transpose weights: W[K][N] -> Wt[n][k] fp16
__global__ __launch_bounds__(1024) void wconv_kernel(const float* __restrict__ wq,
                                                     const float* __restrict__ wk,
                                                     const float* __restrict__ wv,
                                                     const float* __restrict__ wo)
{
    __shared__ float t[32][33];
    int which = blockIdx.z;
    const float* w = (which == 0) ? wq : (which == 1) ? wk : (which == 2) ? wv : wo;
    int kk = blockIdx.y * 32 + threadIdx.y;
    int nn = blockIdx.x * 32 + threadIdx.x;
    t[threadIdx.y][threadIdx.x] = w[kk * DD + nn];
    __syncthreads();
    int on = blockIdx.x * 32 + threadIdx.y;
    int ok = blockIdx.y * 32 + threadIdx.x;
    g_wt16[which][on * DD + ok] = __float2half_rn(t[threadIdx.x][threadIdx.y]);
}

// ---------------------------------------------------------------------------
// Single-pass fp16 HMMA GEMM: C[128,128 tile] = A @ Wt^T + bias
// 256 threads, warp grid 2(m)x4(n), warp tile 64x32, BK=32, 3-stage cp.async.
// mode 0: fp32 out; mode 1: fp16 out *0.125 (Q); mode 2: fp16 out (K/V)
// ---------------------------------------------------------------------------
#define BK 32
#define APITCH 40
#define BUF_BYTES (128 * APITCH * 2)        // 10240 per operand buffer
#define GEMM_STAGE (2 * BUF_BYTES)          // 20480 (A + B)
#define GEMM_SMEM_BYTES (3 * GEMM_STAGE)    // 61440

__device__ __forceinline__ void load_stage(uint32_t sbase, int stage,
                                           const __half* __restrict__ A,
                                           const __half* __restrict__ B,
                                           int m0, int n0, int k0, int tid)
{
    uint32_t so = sbase + stage * GEMM_STAGE;
#pragma unroll
    for (int j = 0; j < 2; j++) {
        int c = tid + (j << 8);                 // 0..511
        int row = c >> 2;                       // 0..127
        int col = (c & 3) << 3;                 // 0,8,16,24
        uint32_t soff = (uint32_t)(row * APITCH + col) * 2;
        cpasync16(so + 0 * BUF_BYTES + soff, A + (size_t)(m0 + row) * DD + k0 + col);
        cpasync16(so + 1 * BUF_BYTES + soff, B + (size_t)(n0 + row) * DD + k0 + col);
    }
}

__device__ __forceinline__ void gemm_tc_body(const __half* __restrict__ A,
                                             const __half* __restrict__ B,
                                             const float* __restrict__ bias,
                                             float* __restrict__ C,
                                             int mode, __half* o16)
{
    extern __shared__ char smem[];
    const uint32_t sbase = smem_to_u32(smem);

    const int tid = threadIdx.x;
    const int lane = tid & 31;
    const int wid = tid >> 5;
    const int wm = (wid >> 2) * 64;     // 0 or 64
    const int wn = (wid & 3) * 32;      // 0,32,64,96
    const int m0 = blockIdx.y * 128;
    const int n0 = blockIdx.x * 128;

    const int a_row = wm + (lane & 15);
    const int a_col = (lane >> 4) << 3;
    const int b_row = wn + ((lane >> 4) << 3) + (lane & 7);
    const int b_col = ((lane >> 3) & 1) << 3;

    float acc[4][4][4];
#pragma unroll
    for (int i = 0; i < 4; i++)
#pragma unroll
        for (int j = 0; j < 4; j++)
#pragma unroll
            for (int r = 0; r < 4; r++) acc[i][j][r] = 0.f;

    load_stage(sbase, 0, A, B, m0, n0, 0, tid);
    cpcommit();
    load_stage(sbase, 1, A, B, m0, n0, BK, tid);
    cpcommit();

    const int NT = DD / BK;             // 32
    int st_idx = 0;
    for (int kt = 0; kt < NT; kt++) {
        if (kt + 2 < NT) {
            int ps = st_idx + 2; if (ps >= 3) ps -= 3;
            load_stage(sbase, ps, A, B, m0, n0, (kt + 2) * BK, tid);
            cpcommit();
            cpwait<2>();
        } else if (kt + 1 < NT) {
            cpwait<1>();
        } else {
            cpwait<0>();
        }
        __syncthreads();

        const uint32_t st = sbase + st_idx * GEMM_STAGE;
#pragma unroll
        for (int ks = 0; ks < 2; ks++) {
            const int kofs = ks * 16;
            uint32_t ah[4][4], bh[2][4];
#pragma unroll
            for (int mt = 0; mt < 4; mt++) {
                uint32_t off = (uint32_t)((a_row + mt * 16) * APITCH + kofs + a_col) * 2;
                ldsm4(ah[mt], st + 0 * BUF_BYTES + off);
            }
#pragma unroll
            for (int nt2 = 0; nt2 < 2; nt2++) {
                uint32_t off = (uint32_t)((b_row + nt2 * 16) * APITCH + kofs + b_col) * 2;
                ldsm4(bh[nt2], st + 1 * BUF_BYTES + off);
            }
#pragma unroll
            for (int mt = 0; mt < 4; mt++)
#pragma unroll
                for (int nt = 0; nt < 4; nt++)
                    mma_f16(acc[mt][nt], ah[mt], &bh[nt >> 1][(nt & 1) * 2]);
        }
        __syncthreads();
        if (++st_idx == 3) st_idx = 0;
    }

    const float sc = (mode == 1) ? 0.125f : 1.0f;
#pragma unroll
    for (int mt = 0; mt < 4; mt++) {
        int row = m0 + wm + mt * 16 + (lane >> 2);
#pragma unroll
        for (int nt = 0; nt < 4; nt++) {
            int col = n0 + wn + nt * 8 + 2 * (lane & 3);
            float b0 = bias[col], b1 = bias[col + 1];
            float v0 = acc[mt][nt][0] + b0, v1 = acc[mt][nt][1] + b1;
            float v2 = acc[mt][nt][2] + b0, v3 = acc[mt][nt][3] + b1;
            size_t off0 = (size_t)row * DD + col;
            size_t off1 = (size_t)(row + 8) * DD + col;
            if (mode == 0) {
                *(float2*)(C + off0) = make_float2(v0, v1);
                *(float2*)(C + off1) = make_float2(v2, v3);
            } else {
                v0 *= sc; v1 *= sc; v2 *= sc; v3 *= sc;
                *(__half2*)(o16 + off0) = __floats2half2_rn(v0, v1);
                *(__half2*)(o16 + off1) = __floats2half2_rn(v2, v3);
            }
        }
    }
}

__global__ __launch_bounds__(256, 2)
void gemm_qkv_tc(const float* __restrict__ bq, const float* __restrict__ bk,
                 const float* __restrict__ bv)
{
    const int z = blockIdx.z;
    if (z == 0)
        gemm_tc_body(g_x16, g_wt16[0], bq, nullptr, 1, g_q16);
    else if (z == 1)
        gemm_tc_body(g_x16, g_wt16[1], bk, nullptr, 2, g_k16);
    else
        gemm_tc_body(g_x16, g_wt16[2], bv, nullptr, 2, g_v16);
}

__global__ __launch_bounds__(256, 2)
void gemm_out_tc(const float* __restrict__ bo, float* __restrict__ out)
{
    gemm_tc_body(g_ao16, g_wt16[3], bo, out, 0, nullptr);
}

// ---------------------------------------------------------------------------
// Tensor-core flash attention, causal, single-pass fp16 everywhere.
// CTA: 64 q rows, 128 threads, 2-stage cp.async K/V pipeline, 4 CTAs/SM.
// Ones-column in V col 64 carries the row-sum l through the PV MMA.
// ---------------------------------------------------------------------------
#define VPITCH 88
#define AQ 0
#define AST 8192
#define SK 0
#define SV 8192
#define ASTAGE (8192 + 64 * VPITCH * 2)     // 19456
#define ATT_SMEM (AST + 2 * ASTAGE)         // 47104

__device__ __forceinline__ void attn_load_stage(uint32_t sb, int stage,
                                                const __half* gk,
                                                const __half* gv,
                                                int k0, int tid)
{
    uint32_t so = sb + AST + stage * ASTAGE;
#pragma unroll
    for (int i = 0; i < 4; i++) {
        int idx = tid + (i << 7);
        int r = idx >> 3, c = idx & 7;
        uint32_t offk = 128u * r + 16u * (c ^ (r & 7));
        size_t g = (size_t)(k0 + r) * DD + c * 8;
        cpasync16(so + SK + offk, gk + g);
        uint32_t offv = (uint32_t)(r * VPITCH + c * 8) * 2;
        cpasync16(so + SV + offv, gv + g);
    }
}

__global__ __launch_bounds__(128, 4) void attn_tc_kernel()
{
    extern __shared__ char sm[];
    const uint32_t sb = smem_to_u32(sm);
    const int tid = threadIdx.x;
    const int lane = tid & 31;
    const int wid = tid >> 5;
    const int bh = blockIdx.y;
    const int b = bh >> 4;
    const int h = bh & 15;
    const int q0 = (int)(gridDim.x - 1 - blockIdx.x) * 64;   // big tiles first

    const size_t tok0 = (size_t)(b * LL);
    const __half* gq = g_q16 + (tok0 + q0) * DD + h * 64;
    const __half* gk = g_k16 + tok0 * DD + h * 64;
    const __half* gv = g_v16 + tok0 * DD + h * 64;

    // kick off stage 0 loads immediately
    attn_load_stage(sb, 0, gk, gv, 0, tid);
    cpcommit();

    // V pad cols 64..87 in BOTH stages: zeros
#pragma unroll
    for (int s = 0; s < 2; s++) {
        char* vb = sm + AST + s * ASTAGE;
        for (int i = tid; i < 64 * 3; i += 128) {
            int r = i / 3, c = i % 3;
            uint32_t off = (uint32_t)(r * VPITCH + 64 + 8 * c) * 2;
            *(uint4*)(vb + SV + off) = make_uint4(0, 0, 0, 0);
        }
    }
    __syncthreads();   // zero-fill visible before ones-column write
#pragma unroll
    for (int s = 0; s < 2; s++) {
        char* vb = sm + AST + s * ASTAGE;
        if (tid < 64) ((__half*)(vb + SV))[tid * VPITCH + 64] = __float2half(1.0f);
    }

    // Load Q tile (swizzled, regular loads)
#pragma unroll
    for (int i = 0; i < 4; i++) {
        int idx = tid + (i << 7);
        int r = idx >> 3, c = idx & 7;
        uint32_t off = 128u * r + 16u * (c ^ (r & 7));
        *(uint4*)(sm + AQ + off) = *(const uint4*)(gq + (size_t)r * DD + c * 8);
    }

    const int arow = 16 * wid + (lane & 15);
    const int ac = lane >> 4;
    const int asw = arow & 7;
    const int brow_in = ((lane >> 4) << 3) + (lane & 7);
    const int bc = (lane >> 3) & 1;
    const int bsw = brow_in & 7;
    const int vrow_in = (lane & 7) + ((lane >> 3) & 1) * 8;
    const int vnc = (lane >> 4);

    float oacc[9][4];
#pragma unroll
    for (int i = 0; i < 9; i++)
#pragma unroll
        for (int j = 0; j < 4; j++) oacc[i][j] = 0.f;
    float m2[2] = {-1e30f, -1e30f};

    const int nk = (q0 >> 6) + 1;
    for (int kt = 0; kt < nk; kt++) {
        if (kt + 1 < nk) {
            attn_load_stage(sb, (kt + 1) & 1, gk, gv, (kt + 1) * 64, tid);
            cpcommit();
            cpwait<1>();
        } else {
            cpwait<0>();
        }
        __syncthreads();
        const uint32_t st = sb + AST + (kt & 1) * ASTAGE;

        // ---- S = Q K^T (single-pass fp16), 16x64 per warp ----
        float sacc[8][4];
#pragma unroll
        for (int i = 0; i < 8; i++)
#pragma unroll
            for (int j = 0; j < 4; j++) sacc[i][j] = 0.f;

#pragma unroll
        for (int ks = 0; ks < 4; ks++) {
            uint32_t qf[4], kf[4][4];
            uint32_t ca = 16u * (uint32_t)((2 * ks + ac) ^ asw);
            ldsm4(qf, sb + AQ + 128u * arow + ca);
            uint32_t cb = 16u * (uint32_t)((2 * ks + bc) ^ bsw);
#pragma unroll
            for (int np = 0; np < 4; np++)
                ldsm4(kf[np], st + SK + 128u * (16 * np + brow_in) + cb);
#pragma unroll
            for (int nt = 0; nt < 8; nt++)
                mma_f16(sacc[nt], qf, &kf[nt >> 1][(nt & 1) * 2]);
        }

        // ---- causal mask (diagonal tile only) ----
        if (kt == nk - 1) {
            const int r0g = 16 * wid + (lane >> 2);
#pragma unroll
            for (int nt = 0; nt < 8; nt++) {
                int kc = 8 * nt + 2 * (lane & 3);
                if (kc > r0g)     sacc[nt][0] = -1e30f;
                if (kc + 1 > r0g) sacc[nt][1] = -1e30f;
                if (kc > r0g + 8)     sacc[nt][2] = -1e30f;
                if (kc + 1 > r0g + 8) sacc[nt][3] = -1e30f;
            }
        }

        // ---- online softmax (log2 domain), P in f16x2 ----
        float mx0 = -1e30f, mx1 = -1e30f;
#pragma unroll
        for (int nt = 0; nt < 8; nt++) {
            mx0 = fmaxf(mx0, fmaxf(sacc[nt][0], sacc[nt][1]));
            mx1 = fmaxf(mx1, fmaxf(sacc[nt][2], sacc[nt][3]));
        }
        mx0 = fmaxf(mx0, __shfl_xor_sync(0xffffffffu, mx0, 1));
        mx0 = fmaxf(mx0, __shfl_xor_sync(0xffffffffu, mx0, 2));
        mx1 = fmaxf(mx1, __shfl_xor_sync(0xffffffffu, mx1, 1));
        mx1 = fmaxf(mx1, __shfl_xor_sync(0xffffffffu, mx1, 2));
        float m2n0 = fmaxf(m2[0], mx0 * L2E);
        float m2n1 = fmaxf(m2[1], mx1 * L2E);
        float al0 = exp2f(m2[0] - m2n0);
        float al1 = exp2f(m2[1] - m2n1);
        m2[0] = m2n0; m2[1] = m2n1;

        uint32_t pf[4][4];
#pragma unroll
        for (int ks = 0; ks < 4; ks++) {
            pf[ks][0] = ex2_f16x2(cvt_f16x2(fmaf(sacc[2*ks][1],   L2E, -m2n0),
                                            fmaf(sacc[2*ks][0],   L2E, -m2n0)));
            pf[ks][1] = ex2_f16x2(cvt_f16x2(fmaf(sacc[2*ks][3],   L2E, -m2n1),
                                            fmaf(sacc[2*ks][2],   L2E, -m2n1)));
            pf[ks][2] = ex2_f16x2(cvt_f16x2(fmaf(sacc[2*ks+1][1], L2E, -m2n0),
                                            fmaf(sacc[2*ks+1][0], L2E, -m2n0)));
            pf[ks][3] = ex2_f16x2(cvt_f16x2(fmaf(sacc[2*ks+1][3], L2E, -m2n1),
                                            fmaf(sacc[2*ks+1][2], L2E, -m2n1)));
        }
#pragma unroll
        for (int nt = 0; nt < 9; nt++) {
            oacc[nt][0] *= al0; oacc[nt][1] *= al0;
            oacc[nt][2] *= al1; oacc[nt][3] *= al1;
        }

        // ---- O += P @ V (single-pass fp16; n=72 incl. ones column) ----
#pragma unroll
        for (int ks = 0; ks < 4; ks++) {
            const uint32_t vrow = (uint32_t)(16 * ks + vrow_in) * (VPITCH * 2);
#pragma unroll
            for (int np = 0; np < 5; np++) {
                uint32_t vf[4];
                uint32_t voff = vrow + 16u * (uint32_t)(2 * np + vnc);
                ldsm4t(vf, st + SV + voff);
                mma_f16(oacc[2 * np], pf[ks], &vf[0]);
                if (np < 4) mma_f16(oacc[2 * np + 1], pf[ks], &vf[2]);
            }
        }
        __syncthreads();
    }

    // ---- normalize and store fp16 (out-proj operand) ----
    const int src = lane & ~3;
    float l0 = __shfl_sync(0xffffffffu, oacc[8][0], src);
    float l1 = __shfl_sync(0xffffffffu, oacc[8][2], src);
    float i0 = 1.0f / l0;
    float i1 = 1.0f / l1;
    const int row0 = q0 + 16 * wid + (lane >> 2);
    __half* base16 = g_ao16 + tok0 * DD + h * 64;
#pragma unroll
    for (int nt = 0; nt < 8; nt++) {
        int col = 8 * nt + 2 * (lane & 3);
        size_t off0 = (size_t)row0 * DD + col;
        size_t off1 = (size_t)(row0 + 8) * DD + col;
        *(__half2*)(base16 + off0) = __floats2half2_rn(oacc[nt][0] * i0, oacc[nt][1] * i0);
        *(__half2*)(base16 + off1) = __floats2half2_rn(oacc[nt][2] * i1, oacc[nt][3] * i1);
    }
}

// ---------------------------------------------------------------------------
extern "C" void kernel_launch(void* const* d_in, const int* in_sizes, int n_in,
                              void* d_out, int out_size)
{
    (void)in_sizes; (void)n_in; (void)out_size;
    const float* x  = (const float*)d_in[0];
    const float* wq = (const float*)d_in[2];
    const float* bq = (const float*)d_in[3];
    const float* wk = (const float*)d_in[4];
    const float* bk = (const float*)d_in[5];
    const float* wv = (const float*)d_in[6];
    const float* bv = (const float*)d_in[7];
    const float* wo = (const float*)d_in[8];
    const float* bo = (const float*)d_in[9];
    float* out = (float*)d_out;

    cudaFuncSetAttribute(gemm_qkv_tc, cudaFuncAttributeMaxDynamicSharedMemorySize,
                         GEMM_SMEM_BYTES);
    cudaFuncSetAttribute(gemm_out_tc, cudaFuncAttributeMaxDynamicSharedMemorySize,
                         GEMM_SMEM_BYTES);
    cudaFuncSetAttribute(attn_tc_kernel, cudaFuncAttributeMaxDynamicSharedMemorySize,
                         ATT_SMEM);

    xconv_kernel<<<(MM * DD / 4) / 256, 256>>>(x);
    wconv_kernel<<<dim3(32, 32, 4), dim3(32, 32)>>>(wq, wk, wv, wo);
    gemm_qkv_tc<<<dim3(DD / 128, MM / 128, 3), 256, GEMM_SMEM_BYTES>>>(bq, bk, bv);
    attn_tc_kernel<<<dim3(LL / 64, BB * HH), 128, ATT_SMEM>>>();
    gemm_out_tc<<<dim3(DD / 128, MM / 128), 256, GEMM_SMEM_BYTES>>>(bo, out);
}